// round 7
// baseline (speedup 1.0000x reference)
#include <cuda_runtime.h>

#define L_TOT    524288
#define M_TOT    (L_TOT / 4)
#define NBATCH   16
#define TILE     2048
#define NTILES   (L_TOT / TILE)   // 256
#define THREADS  256
#define PH2      616              // float2 per phase

// ---------------------------------------------------------------------------
// Compile-time construction of the combined polyphase filter C[r][dd].
// qmf is deterministic: h = kaiser(65, 9)/sum,
// filt[k][n] = h[n]*cos(pi/8*((2k+1)n + 2*(-1)^k)).
// All cos arguments are multiples of pi/8 -> exact 16-entry table.
// ---------------------------------------------------------------------------
__host__ __device__ constexpr double c_i0(double x) {
    double s = 1.0, t = 1.0;
    for (int m = 1; m < 48; m++) { t *= (x * x * 0.25) / ((double)m * m); s += t; }
    return s;
}
__host__ __device__ constexpr double c_sqrt(double x) {
    if (x <= 0.0) return 0.0;
    double g = x > 1.0 ? x : 1.0;
    for (int i = 0; i < 64; i++) g = 0.5 * (g + x / g);
    return g;
}
__host__ __device__ constexpr double c_cos16(int i) {   // cos(pi * i / 8)
    constexpr double c1 = 0.92387953251128675613;  // cos(pi/8)
    constexpr double c2 = 0.70710678118654752440;  // cos(pi/4)
    constexpr double c3 = 0.38268343236508977173;  // cos(3pi/8)
    switch (i & 15) {
        case 0:  return  1.0;  case 1:  return  c1;  case 2:  return  c2;
        case 3:  return  c3;   case 4:  return  0.0; case 5:  return -c3;
        case 6:  return -c2;   case 7:  return -c1;  case 8:  return -1.0;
        case 9:  return -c1;   case 10: return -c2;  case 11: return -c3;
        case 12: return  0.0;  case 13: return  c3;  case 14: return  c2;
        default: return  c1;
    }
}
// one combined coefficient C[r][dd], dd = 4*e + f in [0,128]
__host__ __device__ constexpr float coef(int r, int f, int e) {
    int dd = 4 * e + f;
    if (dd > 128) return 0.0f;
    double w[65] = {};
    double s = 0.0;
    for (int n = 0; n < 65; n++) {
        double t = (n - 32) / 32.0;
        w[n] = c_i0(9.0 * c_sqrt(1.0 - t * t));
        s += w[n];
    }
    double C = 0.0;
    int t0 = (4 - r) & 3;
    for (int t = t0; t <= 64; t += 4) {
        int i = dd - t;
        if (i < 0 || i > 64) continue;
        double ht = w[t] / s, hi = w[i] / s;
        for (int k = 0; k < 4; k++) {
            int sgn = (k & 1) ? -2 : 2;
            int a1 = (((2 * k + 1) * t + sgn) % 16 + 16) % 16;
            int a2 = (((2 * k + 1) * i + sgn) % 16 + 16) % 16;
            C += (ht * c_cos16(a1)) * (hi * c_cos16(a2));
        }
    }
    return (float)C;
}

__device__ __forceinline__ int physi(int i) { return (i & 7) * 78 + (i >> 3); }

// ---------------- edge kernel: exact two-stage edges (uses runtime qmf) -----
__global__ void pqmf_edge_kernel(const float* __restrict__ x,
                                 const float* __restrict__ qmf,
                                 float* __restrict__ y) {
    __shared__ float s_q[260];
    __shared__ float s_sub[4][16];
    __shared__ float s_part[128];

    const int side = blockIdx.x;          // 0 = low edge, 1 = high edge
    const int b    = blockIdx.y;
    const float* xb = x + (size_t)b * L_TOT;
    float*       yb = y + (size_t)b * L_TOT;
    const int tid = threadIdx.x;          // 128 threads

    for (int i = tid; i < 260; i += 128) s_q[i] = qmf[i];
    __syncthreads();

    const int mbase = side ? (M_TOT - 16) : 0;
    if (tid < 64) {
        int k = tid & 3, j = tid >> 2;
        int m = mbase + j;
        float sub = 0.f;
        int pbase = 4 * m - 32;
        for (int s = 0; s <= 64; s++) {
            int pos = pbase + s;
            if (pos >= 0 && pos < L_TOT)
                sub = fmaf(s_q[k * 65 + s], xb[pos], sub);
        }
        s_sub[k][j] = sub;
    }
    __syncthreads();

    float partial = 0.f;
    {
        int nn = tid >> 2, k = tid & 3;
        int n  = side ? (L_TOT - 32 + nn) : nn;
        int t0 = (4 - (n & 3)) & 3;
        for (int t = t0; t <= 64; t += 4) {
            int m = (n + t - 32) >> 2;
            if (m < 0 || m >= M_TOT) continue;
            partial = fmaf(s_q[k * 65 + t], s_sub[k][m - mbase], partial);
        }
    }
    s_part[tid] = partial;
    __syncthreads();
    if (tid < 32) {
        int n = side ? (L_TOT - 32 + tid) : tid;
        yb[n] = s_part[tid * 4] + s_part[tid * 4 + 1] +
                s_part[tid * 4 + 2] + s_part[tid * 4 + 3];
    }
}

// ---------------- main kernel FIR core --------------------------------------
// Coefficients are compile-time immediates (FFMA-imm, rt=1, no RF banking).
// One LDS.64 window load per step; all offsets compile-time.
// B points at this thread's group slot: element 8*tq maps to phys offset tq,
// and element 8*tq + k maps to B[(k&7)*78 + (k>>3)].
template<int R, int F, int E, int STEPS>
__device__ __forceinline__ void fir_steps(const float2* __restrict__ B,
                                          float2 w[8], float2 acc[8]) {
    if constexpr (E < STEPS) {
        constexpr int A = (R + F) >> 2;
        float2 wn = make_float2(0.f, 0.f);
        if constexpr (E + 1 < STEPS)
            wn = B[(((A + E + 8) & 7) * 78) + ((A + E + 8) >> 3)];
        constexpr float c = coef(R, F, E);
        #pragma unroll
        for (int j = 0; j < 8; j++) {
            acc[j].x = fmaf(c, w[j].x, acc[j].x);
            acc[j].y = fmaf(c, w[j].y, acc[j].y);
        }
        #pragma unroll
        for (int j = 0; j < 7; j++) w[j] = w[j + 1];
        w[7] = wn;
        fir_steps<R, F, E + 1, STEPS>(B, w, acc);
    }
}

template<int R, int F>
__device__ __forceinline__ void fir_phase(const float2* __restrict__ sx,
                                          int tq, float2 acc[8]) {
    constexpr int A = (R + F) >> 2;
    constexpr int STEPS = (F == 0) ? 33 : 32;
    const float2* B = sx + (size_t)((R + F) & 3) * PH2 + tq;
    float2 w[8];
    #pragma unroll
    for (int j = 0; j < 8; j++)
        w[j] = B[(((A + j) & 7) * 78) + ((A + j) >> 3)];
    fir_steps<R, F, 0, STEPS>(B, w, acc);
}

template<int R>
__device__ __forceinline__ void fir_all(const float2* __restrict__ sx,
                                        int tq, float2 acc[8]) {
    fir_phase<R, 0>(sx, tq, acc);
    fir_phase<R, 1>(sx, tq, acc);
    fir_phase<R, 2>(sx, tq, acc);
    fir_phase<R, 3>(sx, tq, acc);
}

__global__ __launch_bounds__(THREADS, 4)
void pqmf_main2_kernel(const float* __restrict__ x, float* __restrict__ y) {
    __shared__ float2 s_x2[4][PH2];        // phase-split x (b0,b1); reused for y

    const int tile  = blockIdx.x;
    const int tbase = tile * TILE;
    const float* x0 = x + (size_t)(2 * blockIdx.y) * L_TOT;
    const float* x1 = x0 + L_TOT;
    float* y0 = y + (size_t)(2 * blockIdx.y) * L_TOT;
    float* y1 = y0 + L_TOT;

    for (int idx = threadIdx.x; idx < TILE + 128; idx += THREADS) {
        int pos = tbase - 64 + idx;
        float a0 = 0.f, b0 = 0.f;
        if (pos >= 0 && pos < L_TOT) { a0 = x0[pos]; b0 = x1[pos]; }
        s_x2[idx & 3][physi(idx >> 2)] = make_float2(a0, b0);
    }
    __syncthreads();

    const int warp = threadIdx.x >> 5;
    const int lane = threadIdx.x & 31;
    const int r    = warp & 3;                  // residue owned by this warp
    const int tq   = (warp >> 2) * 32 + lane;   // group index 0..63

    float2 acc[8];
    #pragma unroll
    for (int j = 0; j < 8; j++) acc[j] = make_float2(0.f, 0.f);

    const float2* sx = &s_x2[0][0];
    switch (r) {
        case 0: fir_all<0>(sx, tq, acc); break;
        case 1: fir_all<1>(sx, tq, acc); break;
        case 2: fir_all<2>(sx, tq, acc); break;
        default: fir_all<3>(sx, tq, acc); break;
    }

    __syncthreads();   // all x reads done: reuse s_x2 as y staging

    #pragma unroll
    for (int j = 0; j < 8; j++)
        s_x2[r][j * 78 + tq] = acc[j];
    __syncthreads();

    if (tile > 0 && tile < NTILES - 1) {
        #pragma unroll
        for (int it = 0; it < TILE / THREADS; it++) {
            int idx = it * THREADS + threadIdx.x;
            float2 v = s_x2[idx & 3][physi(idx >> 2)];
            int n = tbase + idx;
            y0[n] = v.x;
            y1[n] = v.y;
        }
    } else {
        for (int idx = threadIdx.x; idx < TILE; idx += THREADS) {
            int n = tbase + idx;
            float2 v = s_x2[idx & 3][physi(idx >> 2)];
            if (n >= 32 && n < L_TOT - 32) {   // edges written by edge kernel
                y0[n] = v.x;
                y1[n] = v.y;
            }
        }
    }
}

extern "C" void kernel_launch(void* const* d_in, const int* in_sizes, int n_in,
                              void* d_out, int out_size) {
    const float* x   = (const float*)d_in[0];
    const float* qmf = (const float*)d_in[1];
    if (n_in >= 2 && in_sizes[0] == 260) {
        x   = (const float*)d_in[1];
        qmf = (const float*)d_in[0];
    }
    float* y = (float*)d_out;

    pqmf_edge_kernel<<<dim3(2, NBATCH), 128>>>(x, qmf, y);
    dim3 grid(NTILES, NBATCH / 2);
    pqmf_main2_kernel<<<grid, THREADS>>>(x, y);
}

// round 9
// speedup vs baseline: 1.5339x; 1.5339x over previous
#include <cuda_runtime.h>
#include <cuda_bf16.h>
#include <cstdint>

#define L_TOT    524288
#define M_TOT    (L_TOT / 4)
#define NBATCH   16
#define TILE_Y   4096
#define NTILES   (L_TOT / TILE_Y)      // 128
#define NTASKS   (NTILES * NBATCH)     // 2048
#define GRID_MAIN 512
#define TASKS_PER_CTA (NTASKS / GRID_MAIN)  // 4

// xs: 4224 fp32 -> 2112 bf16-pair words; skewed: 2112 + 4*(2112/16) = 2640
#define XS_WORDS   2640
#define BS_STRIDE  100                 // words per c-row (100 mod 32 = 4)
#define BS_WORDS   (32 * BS_STRIDE)

// B operand (bf16-pair packed, hi/lo) staged via device globals
__device__ uint32_t g_Bh[32 * 80];
__device__ uint32_t g_Bl[32 * 80];

__device__ __forceinline__ void mma16816(float* d, const uint32_t* a,
                                         uint32_t b0, uint32_t b1) {
    asm volatile(
        "mma.sync.aligned.m16n8k16.row.col.f32.bf16.bf16.f32 "
        "{%0,%1,%2,%3}, {%4,%5,%6,%7}, {%8,%9}, {%0,%1,%2,%3};"
        : "+f"(d[0]), "+f"(d[1]), "+f"(d[2]), "+f"(d[3])
        : "r"(a[0]), "r"(a[1]), "r"(a[2]), "r"(a[3]), "r"(b0), "r"(b1));
}

// ---------------------------------------------------------------------------
// prep: B[c][k] = C[c&3][k-c] (combined polyphase), bf16 hi/lo, pair-packed
// ---------------------------------------------------------------------------
__global__ void prep_B_kernel(const float* __restrict__ qmf) {
    int idx = blockIdx.x * blockDim.x + threadIdx.x;
    if (idx >= 32 * 80) return;
    int c = idx / 80, kp = idx % 80;
    float v[2];
    #pragma unroll
    for (int u = 0; u < 2; u++) {
        int k = 2 * kp + u, dd = k - c;
        float val = 0.f;
        if (dd >= 0 && dd <= 128) {
            int r = c & 3, t0 = (4 - r) & 3;
            for (int t = t0; t <= 64; t += 4) {
                int s = dd - t;
                if (s >= 0 && s <= 64) {
                    #pragma unroll
                    for (int q = 0; q < 4; q++)
                        val += qmf[q * 65 + t] * qmf[q * 65 + s];
                }
            }
        }
        v[u] = val;
    }
    __nv_bfloat16 h0 = __float2bfloat16(v[0]);
    __nv_bfloat16 h1 = __float2bfloat16(v[1]);
    __nv_bfloat16 l0 = __float2bfloat16(v[0] - __bfloat162float(h0));
    __nv_bfloat16 l1 = __float2bfloat16(v[1] - __bfloat162float(h1));
    g_Bh[idx] = ((uint32_t)__bfloat16_as_ushort(h1) << 16) | __bfloat16_as_ushort(h0);
    g_Bl[idx] = ((uint32_t)__bfloat16_as_ushort(l1) << 16) | __bfloat16_as_ushort(l0);
}

// ---------------- edge kernel: exact two-stage edges (proven) ---------------
__global__ void pqmf_edge_kernel(const float* __restrict__ x,
                                 const float* __restrict__ qmf,
                                 float* __restrict__ y) {
    __shared__ float s_q[260];
    __shared__ float s_sub[4][16];
    __shared__ float s_part[128];

    const int side = blockIdx.x;
    const int b    = blockIdx.y;
    const float* xb = x + (size_t)b * L_TOT;
    float*       yb = y + (size_t)b * L_TOT;
    const int tid = threadIdx.x;

    for (int i = tid; i < 260; i += 128) s_q[i] = qmf[i];
    __syncthreads();

    const int mbase = side ? (M_TOT - 16) : 0;
    if (tid < 64) {
        int k = tid & 3, j = tid >> 2;
        int m = mbase + j;
        float sub = 0.f;
        int pbase = 4 * m - 32;
        for (int s = 0; s <= 64; s++) {
            int pos = pbase + s;
            if (pos >= 0 && pos < L_TOT)
                sub = fmaf(s_q[k * 65 + s], xb[pos], sub);
        }
        s_sub[k][j] = sub;
    }
    __syncthreads();

    float partial = 0.f;
    {
        int nn = tid >> 2, k = tid & 3;
        int n  = side ? (L_TOT - 32 + nn) : nn;
        int t0 = (4 - (n & 3)) & 3;
        for (int t = t0; t <= 64; t += 4) {
            int m = (n + t - 32) >> 2;
            if (m < 0 || m >= M_TOT) continue;
            partial = fmaf(s_q[k * 65 + t], s_sub[k][m - mbase], partial);
        }
    }
    s_part[tid] = partial;
    __syncthreads();
    if (tid < 32) {
        int n = side ? (L_TOT - 32 + tid) : tid;
        yb[n] = s_part[tid * 4] + s_part[tid * 4 + 1] +
                s_part[tid * 4 + 2] + s_part[tid * 4 + 3];
    }
}

// ---------------------------------------------------------------------------
// main: bf16 mma.sync GEMM on the Toeplitz view of x (3-pass hi/lo)
// ---------------------------------------------------------------------------
__global__ __launch_bounds__(256, 4)
void pqmf_mma_kernel(const float* __restrict__ x, float* __restrict__ y) {
    __shared__ uint32_t xs_h[XS_WORDS], xs_l[XS_WORDS];
    __shared__ uint32_t bs_h[BS_WORDS], bs_l[BS_WORDS];

    const int tid  = threadIdx.x;
    const int wt   = tid >> 5;     // warp = m-tile (16 rows)
    const int lane = tid & 31;
    const int g    = lane >> 2;    // groupID
    const int tg   = lane & 3;     // threadID-in-group

    // stage B once (pair word kp of row c at bs[c*100 + kp])
    for (int i = tid; i < 32 * 80; i += 256) {
        int c = i / 80, kp = i % 80;
        bs_h[c * BS_STRIDE + kp] = g_Bh[i];
        bs_l[c * BS_STRIDE + kp] = g_Bl[i];
    }

    const int PA = 320 * wt + 20 * g + tg;   // A fragment phys base (words)

    for (int it = 0; it < TASKS_PER_CTA; it++) {
        const int task = blockIdx.x + it * GRID_MAIN;
        const int tile = task & (NTILES - 1);
        const int b    = task >> 7;
        const int t0   = tile * TILE_Y;
        const float* xb = x + (size_t)b * L_TOT;
        float*       yb = y + (size_t)b * L_TOT;

        __syncthreads();   // B visible (iter 0); xs reads of prev task done

        // stage x tile: element pair i2 -> skewed word i2 + 4*(i2>>4)
        for (int i2 = tid; i2 < 2112; i2 += 256) {
            int pos = t0 - 64 + 2 * i2;
            float v0 = 0.f, v1 = 0.f;
            if (pos >= 0 && pos + 1 < L_TOT) {
                float2 xv = *reinterpret_cast<const float2*>(xb + pos);
                v0 = xv.x; v1 = xv.y;
            } else {
                if (pos >= 0 && pos < L_TOT)         v0 = xb[pos];
                if (pos + 1 >= 0 && pos + 1 < L_TOT) v1 = xb[pos + 1];
            }
            __nv_bfloat16 h0 = __float2bfloat16(v0);
            __nv_bfloat16 h1 = __float2bfloat16(v1);
            __nv_bfloat16 l0 = __float2bfloat16(v0 - __bfloat162float(h0));
            __nv_bfloat16 l1 = __float2bfloat16(v1 - __bfloat162float(h1));
            int pw = i2 + 4 * (i2 >> 4);
            xs_h[pw] = ((uint32_t)__bfloat16_as_ushort(h1) << 16) |
                       __bfloat16_as_ushort(h0);
            xs_l[pw] = ((uint32_t)__bfloat16_as_ushort(l1) << 16) |
                       __bfloat16_as_ushort(l0);
        }
        __syncthreads();

        float d[4][4];
        #pragma unroll
        for (int nt = 0; nt < 4; nt++)
            #pragma unroll
            for (int q = 0; q < 4; q++) d[nt][q] = 0.f;

        #pragma unroll
        for (int s = 0; s < 10; s++) {
            const int pw = PA + 8 * s + 4 * (s >> 1);   // compile-time offset
            uint32_t ah[4], al[4];
            ah[0] = xs_h[pw];       ah[2] = xs_h[pw + 4];
            ah[1] = xs_h[pw + 160]; ah[3] = xs_h[pw + 164];
            al[0] = xs_l[pw];       al[2] = xs_l[pw + 4];
            al[1] = xs_l[pw + 160]; al[3] = xs_l[pw + 164];
            #pragma unroll
            for (int nt = 0; nt < 4; nt++) {
                const int pb = 800 * nt + 100 * g + tg + 8 * s;
                uint32_t bh0 = bs_h[pb], bh1 = bs_h[pb + 4];
                uint32_t bl0 = bs_l[pb], bl1 = bs_l[pb + 4];
                mma16816(d[nt], ah, bh0, bh1);   // hi*hi
                mma16816(d[nt], al, bh0, bh1);   // lo*hi
                mma16816(d[nt], ah, bl0, bl1);   // hi*lo
            }
        }

        // epilogue: d[nt] rows (16wt+g, +8), cols 8nt + 2tg + {0,1}
        const int row0 = 16 * wt + g;
        const bool skip_lo = (tile == 0) && (row0 == 0);
        const bool skip_hi = (tile == NTILES - 1) && (row0 + 8 == 127);
        #pragma unroll
        for (int nt = 0; nt < 4; nt++) {
            int n_lo = t0 + 32 * row0 + 8 * nt + 2 * tg;
            if (!skip_lo)
                *reinterpret_cast<float2*>(yb + n_lo) =
                    make_float2(d[nt][0], d[nt][1]);
            if (!skip_hi)
                *reinterpret_cast<float2*>(yb + n_lo + 256) =
                    make_float2(d[nt][2], d[nt][3]);
        }
    }
}

extern "C" void kernel_launch(void* const* d_in, const int* in_sizes, int n_in,
                              void* d_out, int out_size) {
    const float* x   = (const float*)d_in[0];
    const float* qmf = (const float*)d_in[1];
    if (n_in >= 2 && in_sizes[0] == 260) {
        x   = (const float*)d_in[1];
        qmf = (const float*)d_in[0];
    }
    float* y = (float*)d_out;

    prep_B_kernel<<<10, 256>>>(qmf);
    pqmf_edge_kernel<<<dim3(2, NBATCH), 128>>>(x, qmf, y);
    pqmf_mma_kernel<<<GRID_MAIN, 256>>>(x, y);
}